// round 9
// baseline (speedup 1.0000x reference)
#include <cuda_runtime.h>

// RK4 over tiny MLP (3 -> 8 -> 1, ReLU), per-row, fp32.
// R8:
//  - NO grid-stride loop: 1 group (4 rows) per thread, grid=8192. The 4-iter
//    loop re-synchronized all warps at each iteration boundary -> correlated
//    LDG bursts -> L1tex queue spikes -> issue pinned at 68%. One batch of
//    loads per thread lets CTA-level staggering pipeline loads vs compute.
//  - __launch_bounds__(256,6): 40 regs, ~75% occupancy ceiling.
//  - b2 folded into chain constants (y0b, y0d): stage accumulators start at
//    zero (RZ), chains are one op shorter, 4 acc-init movs gone.

typedef unsigned long long u64;

#define DT       0.25f
#define HALF_DT  0.125f
#define DT6      (0.25f / 6.0f)

__device__ __forceinline__ u64 pack2(float lo, float hi) {
    u64 r;
    asm("mov.b64 %0, {%1, %2};" : "=l"(r) : "f"(lo), "f"(hi));
    return r;
}
__device__ __forceinline__ u64 ffma2(u64 a, u64 b, u64 c) {
    u64 d;
    asm("fma.rn.f32x2 %0, %1, %2, %3;" : "=l"(d) : "l"(a), "l"(b), "l"(c));
    return d;
}
// ReLU both lanes in one asm block (ptxas allocates halves onto the pair).
__device__ __forceinline__ u64 relu2(u64 t) {
    u64 d;
    asm("{\n\t"
        ".reg .f32 lo, hi;\n\t"
        "mov.b64 {lo, hi}, %1;\n\t"
        "max.f32 lo, lo, 0f00000000;\n\t"
        "max.f32 hi, hi, 0f00000000;\n\t"
        "mov.b64 %0, {lo, hi};\n\t"
        "}" : "=l"(d) : "l"(t));
    return d;
}
// Horizontal sum of a pair -> scalar.
__device__ __forceinline__ float hsum(u64 v) {
    float lo, hi;
    asm("mov.b64 {%0, %1}, %2;" : "=f"(lo), "=f"(hi) : "l"(v));
    return lo + hi;
}

struct WeightsP {
    u64 w0[4];   // y0 coefficients, lanes = hidden units (2k, 2k+1)
    u64 w1[4];   // y1 coefficients
    u64 w2[4];   // y2 coefficients
    u64 bb[4];   // b1
    u64 v[4];    // W2
};

// S = sum_j v_j * relu(w0_j*ys + C_j), accumulated from zero (RZ).
__device__ __forceinline__ u64 mlp_acc0(const WeightsP& W, const u64 (&C)[4], u64 ys) {
    u64 acc = 0ull;
#pragma unroll
    for (int k = 0; k < 4; k++) {
        u64 t = relu2(ffma2(W.w0[k], ys, C[k]));
        acc = ffma2(W.v[k], t, acc);
    }
    return acc;
}

// One row of RK4. y0b = y0 + HALF_DT*b2, y0d = y0 + DT*b2 precomputed by caller.
__device__ __forceinline__ float rk4_row(const WeightsP& W, float y0, float b2s,
                                         u64 y1b, u64 y2b) {
    // Per-row constants c_j = b1_j + w1_j*y1 + w2_j*y2
    u64 C[4];
#pragma unroll
    for (int k = 0; k < 4; k++)
        C[k] = ffma2(W.w2[k], y2b, ffma2(W.w1[k], y1b, W.bb[k]));

    float y0b = fmaf(HALF_DT, b2s, y0);
    float y0d = fmaf(DT, b2s, y0);

    float s1 = hsum(mlp_acc0(W, C, pack2(y0, y0)));
    float ys2 = fmaf(HALF_DT, s1, y0b);
    float s2 = hsum(mlp_acc0(W, C, pack2(ys2, ys2)));
    float ys3 = fmaf(HALF_DT, s2, y0b);
    float s3 = hsum(mlp_acc0(W, C, pack2(ys3, ys3)));
    float ys4 = fmaf(DT, s3, y0d);
    float s4 = hsum(mlp_acc0(W, C, pack2(ys4, ys4)));

    // k_i = s_i + b2; K = s1+2(s2+s3)+s4 + 6*b2
    // y = y0 + DT6*K = fmaf(DT6, Ksum, y0d)   [y0d absorbs DT6*6*b2 = DT*b2]
    float Ks = fmaf(2.0f, s2 + s3, s1 + s4);
    return fmaf(DT6, Ks, y0d);
}

template <bool GUARDED>
__global__ void __launch_bounds__(256, 6)
node_rk4_kernel(const float* __restrict__ x,
                const float* __restrict__ W1,
                const float* __restrict__ b1,
                const float* __restrict__ W2,
                const float* __restrict__ b2,
                float* __restrict__ out,
                int ngroups)   // ngroups = rows/4
{
    int g = blockIdx.x * blockDim.x + threadIdx.x;
    if (GUARDED && g >= ngroups) return;

    // ---- x data: 4 rows = 12 floats = 3 coalesced float4 loads ----
    const float4* x4 = reinterpret_cast<const float4*>(x);
    float4 fa = __ldg(&x4[3 * g + 0]);
    float4 fb = __ldg(&x4[3 * g + 1]);
    float4 fc = __ldg(&x4[3 * g + 2]);

    // ---- Weights (lane-uniform vector LDGs -> L1 broadcast) ----
    const float4* W14 = reinterpret_cast<const float4*>(W1);
    float4 wA = __ldg(&W14[0]);
    float4 wB = __ldg(&W14[1]);
    float4 wC = __ldg(&W14[2]);
    float4 wD = __ldg(&W14[3]);
    float4 wE = __ldg(&W14[4]);
    float4 wF = __ldg(&W14[5]);
    const float4* b14 = reinterpret_cast<const float4*>(b1);
    float4 bA = __ldg(&b14[0]);
    float4 bB = __ldg(&b14[1]);
    const float4* W24 = reinterpret_cast<const float4*>(W2);
    float4 vA = __ldg(&W24[0]);
    float4 vB = __ldg(&W24[1]);
    float  b2s = __ldg(b2);

    WeightsP W;
    W.w0[0] = pack2(wA.x, wA.w);
    W.w0[1] = pack2(wB.z, wC.y);
    W.w0[2] = pack2(wD.x, wD.w);
    W.w0[3] = pack2(wE.z, wF.y);

    W.w1[0] = pack2(wA.y, wB.x);
    W.w1[1] = pack2(wB.w, wC.z);
    W.w1[2] = pack2(wD.y, wE.x);
    W.w1[3] = pack2(wE.w, wF.z);

    W.w2[0] = pack2(wA.z, wB.y);
    W.w2[1] = pack2(wC.x, wC.w);
    W.w2[2] = pack2(wD.z, wE.y);
    W.w2[3] = pack2(wF.x, wF.w);

    W.bb[0] = pack2(bA.x, bA.y);
    W.bb[1] = pack2(bA.z, bA.w);
    W.bb[2] = pack2(bB.x, bB.y);
    W.bb[3] = pack2(bB.z, bB.w);

    W.v[0] = pack2(vA.x, vA.y);
    W.v[1] = pack2(vA.z, vA.w);
    W.v[2] = pack2(vB.x, vB.y);
    W.v[3] = pack2(vB.z, vB.w);

    // ---- 4 rows ----
    float r0 = rk4_row(W, fa.x, b2s, pack2(fa.y, fa.y), pack2(fa.z, fa.z));
    float r1 = rk4_row(W, fa.w, b2s, pack2(fb.x, fb.x), pack2(fb.y, fb.y));
    float r2 = rk4_row(W, fb.z, b2s, pack2(fb.w, fb.w), pack2(fc.x, fc.x));
    float r3 = rk4_row(W, fc.y, b2s, pack2(fc.z, fc.z), pack2(fc.w, fc.w));

    reinterpret_cast<float4*>(out)[g] = make_float4(r0, r1, r2, r3);
}

extern "C" void kernel_launch(void* const* d_in, const int* in_sizes, int n_in,
                              void* d_out, int out_size)
{
    const float* x  = (const float*)d_in[0];
    const float* W1 = (const float*)d_in[1];
    const float* b1 = (const float*)d_in[2];
    const float* W2 = (const float*)d_in[3];
    const float* b2 = (const float*)d_in[4];
    float* out = (float*)d_out;

    int rows    = in_sizes[0] / 3;       // 8388608
    int ngroups = rows / 4;              // 2097152
    int block = 256;
    int grid  = (ngroups + block - 1) / block;   // 8192

    bool exact = (rows % 4 == 0) && (ngroups % block == 0);

    if (exact)
        node_rk4_kernel<false><<<grid, block>>>(x, W1, b1, W2, b2, out, ngroups);
    else
        node_rk4_kernel<true ><<<grid, block>>>(x, W1, b1, W2, b2, out, ngroups);
}

// round 10
// speedup vs baseline: 1.5635x; 1.5635x over previous
#include <cuda_runtime.h>
#include <cuda_fp16.h>

// RK4 over tiny MLP (3 -> 8 -> 1, ReLU), per-row, fp32 I/O, fp16x2 core.
// R9: rows-in-lanes fp16 packing. Tolerance is 1e-3 and we were at 2e-8 —
// spend precision to cut instructions:
//  - half2 lanes = (rowA, rowB): ReLU is ONE __hmax2 (no unpack movs),
//    and each lane keeps its own k -> NO horizontal sum / broadcast at all.
//  - Stage chain ys_next = __hfma2(dt, s, y0p) stays packed end-to-end.
//  - Only the final y = y0d + DT6*K runs in fp32.
//  ~68 instr/row vs 103 in the fp32-packed kernels (-34%).
// Weight-load amortization kept (R8: per-thread weight LDGs without a loop
// drove L1 to 71% and dur to 51us): 16 rows/thread, grid 2048.

#define DT       0.25f
#define HALF_DT  0.125f
#define DT6      (0.25f / 6.0f)

struct HW {
    __half2 w0[8];   // broadcast (w,w): y0 coefficient of unit j
    __half2 w1[8];   // y1 coefficient
    __half2 w2[8];   // y2 coefficient
    __half2 b1[8];
    __half2 v[8];    // W2
};

// One RK4 step for a ROW PAIR riding the two fp16 lanes.
__device__ __forceinline__ float2 rk4_pair(const HW& W,
                                           float y0A, float y1A, float y2A,
                                           float y0B, float y1B, float y2B,
                                           float b2s)
{
    const __half2 zero2 = __float2half2_rn(0.0f);
    const __half2 hdt2  = __float2half2_rn(HALF_DT);
    const __half2 dt2   = __float2half2_rn(DT);
    const __half2 two2  = __float2half2_rn(2.0f);

    // Per-row constants c_j = b1_j + w1_j*y1 + w2_j*y2, lanes = rows.
    __half2 y1p = __floats2half2_rn(y1A, y1B);
    __half2 y2p = __floats2half2_rn(y2A, y2B);
    __half2 C[8];
#pragma unroll
    for (int j = 0; j < 8; j++)
        C[j] = __hfma2(W.w1[j], y1p, __hfma2(W.w2[j], y2p, W.b1[j]));

    // b2 folded into chain bases: k_i = s_i + b2.
    float y0bA = fmaf(HALF_DT, b2s, y0A);
    float y0bB = fmaf(HALF_DT, b2s, y0B);
    float y0dA = fmaf(DT, b2s, y0A);
    float y0dB = fmaf(DT, b2s, y0B);
    __half2 y0bp = __floats2half2_rn(y0bA, y0bB);
    __half2 y0dp = __floats2half2_rn(y0dA, y0dB);

    // One MLP eval (both rows at once): s = sum_j v_j * relu(w0_j*ys + C_j)
    auto stage = [&](__half2 ys) -> __half2 {
        __half2 acc = zero2;
#pragma unroll
        for (int j = 0; j < 8; j++) {
            __half2 t = __hfma2(W.w0[j], ys, C[j]);
            t = __hmax2(t, zero2);                 // packed ReLU, 1 instr
            acc = __hfma2(W.v[j], t, acc);
        }
        return acc;
    };

    __half2 ys1 = __floats2half2_rn(y0A, y0B);
    __half2 s1  = stage(ys1);
    __half2 ys2 = __hfma2(hdt2, s1, y0bp);         // y0 + hdt*(s1+b2)
    __half2 s2  = stage(ys2);
    __half2 ys3 = __hfma2(hdt2, s2, y0bp);
    __half2 s3  = stage(ys3);
    __half2 ys4 = __hfma2(dt2, s3, y0dp);          // y0 + dt*(s3+b2)
    __half2 s4  = stage(ys4);

    // K = s1 + 2(s2+s3) + s4 ; y = y0d + DT6*K  (y0d absorbs DT*b2)
    __half2 t23 = __hadd2(s2, s3);
    __half2 t14 = __hadd2(s1, s4);
    __half2 Kp  = __hfma2(two2, t23, t14);

    float outA = fmaf(DT6, __low2float(Kp),  y0dA);
    float outB = fmaf(DT6, __high2float(Kp), y0dB);
    return make_float2(outA, outB);
}

template <bool GUARDED>
__global__ void __launch_bounds__(256, 3)
node_rk4_kernel(const float* __restrict__ x,
                const float* __restrict__ W1,
                const float* __restrict__ b1,
                const float* __restrict__ W2,
                const float* __restrict__ b2,
                float* __restrict__ out,
                int ngroups)   // ngroups = rows/4
{
    // ---- Load weights once per thread (lane-uniform -> L1 broadcast) ----
    const float4* W14 = reinterpret_cast<const float4*>(W1);
    float4 wA = __ldg(&W14[0]);
    float4 wB = __ldg(&W14[1]);
    float4 wC = __ldg(&W14[2]);
    float4 wD = __ldg(&W14[3]);
    float4 wE = __ldg(&W14[4]);
    float4 wF = __ldg(&W14[5]);
    const float4* b14 = reinterpret_cast<const float4*>(b1);
    float4 bA = __ldg(&b14[0]);
    float4 bB = __ldg(&b14[1]);
    const float4* W24 = reinterpret_cast<const float4*>(W2);
    float4 vA = __ldg(&W24[0]);
    float4 vB = __ldg(&W24[1]);
    float  b2s = __ldg(b2);

    // Broadcast each weight into both half2 lanes (one CVT each, once/thread,
    // amortized over 16 rows).
    HW W;
    W.w0[0] = __float2half2_rn(wA.x);  W.w0[1] = __float2half2_rn(wA.w);
    W.w0[2] = __float2half2_rn(wB.z);  W.w0[3] = __float2half2_rn(wC.y);
    W.w0[4] = __float2half2_rn(wD.x);  W.w0[5] = __float2half2_rn(wD.w);
    W.w0[6] = __float2half2_rn(wE.z);  W.w0[7] = __float2half2_rn(wF.y);

    W.w1[0] = __float2half2_rn(wA.y);  W.w1[1] = __float2half2_rn(wB.x);
    W.w1[2] = __float2half2_rn(wB.w);  W.w1[3] = __float2half2_rn(wC.z);
    W.w1[4] = __float2half2_rn(wD.y);  W.w1[5] = __float2half2_rn(wE.x);
    W.w1[6] = __float2half2_rn(wE.w);  W.w1[7] = __float2half2_rn(wF.z);

    W.w2[0] = __float2half2_rn(wA.z);  W.w2[1] = __float2half2_rn(wB.y);
    W.w2[2] = __float2half2_rn(wC.x);  W.w2[3] = __float2half2_rn(wC.w);
    W.w2[4] = __float2half2_rn(wD.z);  W.w2[5] = __float2half2_rn(wE.y);
    W.w2[6] = __float2half2_rn(wF.x);  W.w2[7] = __float2half2_rn(wF.w);

    W.b1[0] = __float2half2_rn(bA.x);  W.b1[1] = __float2half2_rn(bA.y);
    W.b1[2] = __float2half2_rn(bA.z);  W.b1[3] = __float2half2_rn(bA.w);
    W.b1[4] = __float2half2_rn(bB.x);  W.b1[5] = __float2half2_rn(bB.y);
    W.b1[6] = __float2half2_rn(bB.z);  W.b1[7] = __float2half2_rn(bB.w);

    W.v[0]  = __float2half2_rn(vA.x);  W.v[1]  = __float2half2_rn(vA.y);
    W.v[2]  = __float2half2_rn(vA.z);  W.v[3]  = __float2half2_rn(vA.w);
    W.v[4]  = __float2half2_rn(vB.x);  W.v[5]  = __float2half2_rn(vB.y);
    W.v[6]  = __float2half2_rn(vB.z);  W.v[7]  = __float2half2_rn(vB.w);

    const float4* x4   = reinterpret_cast<const float4*>(x);
    float4*       out4 = reinterpret_cast<float4*>(out);

    int g = blockIdx.x * blockDim.x + threadIdx.x;
    const int stride = gridDim.x * blockDim.x;

#pragma unroll
    for (int it = 0; it < 4; it++, g += stride) {
        if (!GUARDED || g < ngroups) {
            // 4 rows = 12 floats = 3 coalesced float4 loads
            float4 fa = __ldg(&x4[3 * g + 0]);
            float4 fb = __ldg(&x4[3 * g + 1]);
            float4 fc = __ldg(&x4[3 * g + 2]);

            // rows 0,1 in one half2 pair; rows 2,3 in the other
            float2 r01 = rk4_pair(W, fa.x, fa.y, fa.z,   fa.w, fb.x, fb.y, b2s);
            float2 r23 = rk4_pair(W, fb.z, fb.w, fc.x,   fc.y, fc.z, fc.w, b2s);

            out4[g] = make_float4(r01.x, r01.y, r23.x, r23.y);
        }
    }
}

extern "C" void kernel_launch(void* const* d_in, const int* in_sizes, int n_in,
                              void* d_out, int out_size)
{
    const float* x  = (const float*)d_in[0];
    const float* W1 = (const float*)d_in[1];
    const float* b1 = (const float*)d_in[2];
    const float* W2 = (const float*)d_in[3];
    const float* b2 = (const float*)d_in[4];
    float* out = (float*)d_out;

    int rows    = in_sizes[0] / 3;       // 8388608
    int ngroups = rows / 4;              // 2097152
    int block = 256;
    int total_threads = (ngroups + 3) / 4;   // 4 groups (16 rows) per thread
    int grid  = (total_threads + block - 1) / block;   // 2048

    bool exact = (rows % 4 == 0) &&
                 (ngroups % 4 == 0) &&
                 ((long long)grid * block * 4 == (long long)ngroups);

    if (exact)
        node_rk4_kernel<false><<<grid, block>>>(x, W1, b1, W2, b2, out, ngroups);
    else
        node_rk4_kernel<true ><<<grid, block>>>(x, W1, b1, W2, b2, out, ngroups);
}